// round 6
// baseline (speedup 1.0000x reference)
#include <cuda_runtime.h>
#include <cstdint>

// ---------------- model constants ----------------
#define BB 16
#define N0 512
#define N1 256
#define N2 128
#define F0c 64
#define F1c 128
#define F2c 256
#define KK 8
#define FC_OUT 512
#define FLATD (N2 * F2c)        // 32768
#define EPSC 1e-9f
#define ZCUT 40.0f              // exp(-z) below this is numerically zero vs tol

// ---------------- scratch (device globals, no allocs) ----------------
__device__ float g_X0[BB * N0 * (F0c + KK * F0c)];   // [8192, 576]
__device__ float g_H0p[BB * N1 * F1c];
__device__ float g_C1[BB * N1 * 3];
__device__ float g_X1[BB * N1 * (F1c + KK * F1c)];   // [4096, 1152]
__device__ float g_Flat[BB * N2 * F2c];
__device__ float g_part[128][BB * FC_OUT];

// ---------------- tf32 helpers ----------------
__device__ __forceinline__ uint32_t f2tf(float x) {
    uint32_t r;
    asm("cvt.rna.tf32.f32 %0, %1;" : "=r"(r) : "f"(x));
    return r;
}
__device__ __forceinline__ void mma8(float* c,
        uint32_t a0, uint32_t a1, uint32_t a2, uint32_t a3,
        uint32_t b0, uint32_t b1) {
    asm volatile(
        "mma.sync.aligned.m16n8k8.row.col.f32.tf32.tf32.f32 "
        "{%0,%1,%2,%3},{%4,%5,%6,%7},{%8,%9},{%0,%1,%2,%3};"
        : "+f"(c[0]), "+f"(c[1]), "+f"(c[2]), "+f"(c[3])
        : "r"(a0), "r"(a1), "r"(a2), "r"(a3), "r"(b0), "r"(b1));
}

// =================================================================
// Fused message passing: tf32 mma, exp-sparsified A build,
// single-barrier-per-tile pipeline (build is warp-self-sufficient).
// =================================================================
template <int F>
struct MsgSmem {
    float4 Ci[16];
    float  Rni[16];
    float  U[16][KK];
    float  W[16][KK];
    float  Umin[16];
    uint32_t A[2][128][36];
    uint32_t Vt[2][32][F + 8];
    unsigned short wIdx[8][64];
    float  wD2[8][64];
    float  wCs[8][64];
};

template <int F, int N>
__global__ __launch_bounds__(256, 2) void msg_kernel(
        const float* __restrict__ V, const float* __restrict__ C,
        const float* __restrict__ gkw, const float* __restrict__ gkb,
        const float* __restrict__ acw, const float* __restrict__ acb,
        float* __restrict__ X) {
    constexpr int TI = 16, TJ = 32, XW = F + KK * F;
    constexpr int WARPS_M = (F == 128) ? 2 : 4;
    constexpr int WARPS_N = 8 / WARPS_M;
    constexpr int WM = 128 / WARPS_M;
    constexpr int WN = F / WARPS_N;         // 32
    constexpr int TM = WM / 16;
    constexpr int TN = WN / 8;              // 4
    constexpr int VLD = TJ * (F / 4) / 256; // float4 per thread per V tile
    constexpr int T = N / TJ;

    extern __shared__ char smem_raw[];
    auto& S = *reinterpret_cast<MsgSmem<F>*>(smem_raw);

    const int b = blockIdx.y;
    const int i0 = blockIdx.x * TI;
    const int tid = threadIdx.x;
    const int wid = tid >> 5, lane = tid & 31;
    const int g = lane >> 2, cc = lane & 3;
    const int warp_m = wid / WARPS_N, warp_n = wid % WARPS_N;

    // ---- setup ----
    if (tid < TI) {
        int i = i0 + tid;
        float x = C[((size_t)b * N + i) * 3 + 0];
        float y = C[((size_t)b * N + i) * 3 + 1];
        float z = C[((size_t)b * N + i) * 3 + 2];
        float l2 = x * x + y * y + z * z;
        S.Ci[tid] = make_float4(x, y, z, l2);
        S.Rni[tid] = rsqrtf(l2 + EPSC);
    }
    {   // fused gates: 256 threads = 2 gates x 16 rows x 8 k
        int gate = tid >> 7;
        int r = (tid >> 3) & (TI - 1);
        int k = tid & 7;
        const float* wgt = gate ? acw : gkw;
        float s = gate ? acb[k] : gkb[k];
        const float* vrow = V + ((size_t)b * N + i0 + r) * F;
#pragma unroll 8
        for (int f = 0; f < F; ++f) s += vrow[f] * wgt[f * KK + k];
        if (gate) {
            S.W[r][k] = 1.f / (1.f + __expf(-s));
        } else {
            float u = fmaxf(s, 0.f) + log1pf(__expf(-fabsf(s)));
            S.U[r][k] = u;
            float um = u;
            um = fminf(um, __shfl_xor_sync(0xffffffffu, um, 1));
            um = fminf(um, __shfl_xor_sync(0xffffffffu, um, 2));
            um = fminf(um, __shfl_xor_sync(0xffffffffu, um, 4));
            if (k == 0) S.Umin[r] = um;
        }
    }
    // copy V rows into first F cols of X
    for (int t = tid; t < TI * (F / 4); t += 256) {
        int i = t / (F / 4), fq = t % (F / 4);
        float4 vv = reinterpret_cast<const float4*>(V + ((size_t)b * N + i0 + i) * F)[fq];
        reinterpret_cast<float4*>(X + ((size_t)b * N + i0 + i) * XW)[fq] = vv;
    }
    __syncthreads();   // gates/Ci visible

    // ---- warp-self-sufficient A-tile builder ----
    // warp wid owns rows i = wid, wid+8; lane owns column jj = lane.
    // coords for column j passed in regs (loaded by this lane from gmem).
    auto build = [&](int buf, float cx, float cy, float cz) {
        float l2 = cx * cx + cy * cy + cz * cz;
        float rnj = rsqrtf(l2 + EPSC);
        int wcnt = 0;
#pragma unroll
        for (int s = 0; s < 2; ++s) {
            int i = wid + s * 8, jj = lane;
            float4 ci = S.Ci[i];
            float dot = ci.x * cx + ci.y * cy + ci.z * cz;
            float d2 = fabsf(ci.w + l2 - 2.f * dot) + EPSC;
            bool near = (d2 * S.Umin[i] <= ZCUT);
            if (!near) {
#pragma unroll
                for (int k = 0; k < KK; ++k) S.A[buf][(k << 4) | i][jj] = 0u;
            }
            unsigned mask = __ballot_sync(0xffffffffu, near);
            if (near) {
                int slot = wcnt + __popc(mask & ((1u << lane) - 1u));
                S.wIdx[wid][slot] = (unsigned short)((i << 5) | jj);
                S.wD2[wid][slot] = d2;
                S.wCs[wid][slot] = dot * S.Rni[i] * rnj;
            }
            wcnt += __popc(mask);
        }
        __syncwarp();
        const int work = wcnt * KK;
        for (int t = lane; t < work; t += 32) {
            int e = t >> 3, k = t & 7;
            int p = S.wIdx[wid][e];
            int i = p >> 5, jj = p & 31;
            float d2 = S.wD2[wid][e], cs = S.wCs[wid][e];
            float u = S.U[i][k], w = S.W[i][k];
            float z = d2 * u;
            float ex = (z > ZCUT) ? 0.f : __expf(-z);
            S.A[buf][(k << 4) | i][jj] = f2tf(ex * (w * cs + 1.f - w));
        }
    };

    // stage tile 0 + build(0)
    {
#pragma unroll
        for (int s = 0; s < VLD; ++s) {
            int idx = tid + s * 256;
            int j = idx / (F / 4), fq = idx % (F / 4);
            float4 vv = reinterpret_cast<const float4*>(V + ((size_t)b * N + j) * F)[fq];
            S.Vt[0][j][fq * 4 + 0] = f2tf(vv.x);
            S.Vt[0][j][fq * 4 + 1] = f2tf(vv.y);
            S.Vt[0][j][fq * 4 + 2] = f2tf(vv.z);
            S.Vt[0][j][fq * 4 + 3] = f2tf(vv.w);
        }
        const float* cp = C + ((size_t)b * N + lane) * 3;
        build(0, cp[0], cp[1], cp[2]);
    }
    __syncthreads();

    float acc[TM][TN][4];
#pragma unroll
    for (int tm = 0; tm < TM; ++tm)
#pragma unroll
        for (int tn = 0; tn < TN; ++tn)
#pragma unroll
            for (int q = 0; q < 4; ++q) acc[tm][tn][q] = 0.f;

    for (int t = 0; t < T; ++t) {
        const int cur = t & 1, nxt = cur ^ 1;
        const bool more = (t + 1 < T);
        // prefetch tile t+1 (V tile + this lane's column coords)
        float4 vreg[VLD];
        float cx = 0.f, cy = 0.f, cz = 0.f;
        if (more) {
            int j0n = (t + 1) * TJ;
#pragma unroll
            for (int s = 0; s < VLD; ++s) {
                int idx = tid + s * 256;
                int j = idx / (F / 4), fq = idx % (F / 4);
                vreg[s] = reinterpret_cast<const float4*>(
                    V + ((size_t)b * N + j0n + j) * F)[fq];
            }
            const float* cp = C + ((size_t)b * N + j0n + lane) * 3;
            cx = cp[0]; cy = cp[1]; cz = cp[2];
        }
        // mma on tile t
#pragma unroll
        for (int ks = 0; ks < 4; ++ks) {
            uint32_t af[TM][4];
#pragma unroll
            for (int tm = 0; tm < TM; ++tm) {
                int r = warp_m * WM + tm * 16;
                af[tm][0] = S.A[cur][r + g][ks * 8 + cc];
                af[tm][1] = S.A[cur][r + g + 8][ks * 8 + cc];
                af[tm][2] = S.A[cur][r + g][ks * 8 + cc + 4];
                af[tm][3] = S.A[cur][r + g + 8][ks * 8 + cc + 4];
            }
#pragma unroll
            for (int tn = 0; tn < TN; ++tn) {
                int nb = warp_n * WN + tn * 8;
                uint32_t b0 = S.Vt[cur][ks * 8 + cc][nb + g];
                uint32_t b1 = S.Vt[cur][ks * 8 + cc + 4][nb + g];
#pragma unroll
                for (int tm = 0; tm < TM; ++tm)
                    mma8(acc[tm][tn], af[tm][0], af[tm][1], af[tm][2], af[tm][3], b0, b1);
            }
        }
        // stage + build tile t+1 (no cross-warp deps)
        if (more) {
#pragma unroll
            for (int s = 0; s < VLD; ++s) {
                int idx = tid + s * 256;
                int j = idx / (F / 4), fq = idx % (F / 4);
                S.Vt[nxt][j][fq * 4 + 0] = f2tf(vreg[s].x);
                S.Vt[nxt][j][fq * 4 + 1] = f2tf(vreg[s].y);
                S.Vt[nxt][j][fq * 4 + 2] = f2tf(vreg[s].z);
                S.Vt[nxt][j][fq * 4 + 3] = f2tf(vreg[s].w);
            }
            build(nxt, cx, cy, cz);
        }
        __syncthreads();   // single barrier per tile
    }

    // write M section of X: row m = k*16+i
#pragma unroll
    for (int tm = 0; tm < TM; ++tm) {
#pragma unroll
        for (int half = 0; half < 2; ++half) {
            int m = warp_m * WM + tm * 16 + g + half * 8;
            int k = m >> 4, i = m & 15;
            float* xr = X + ((size_t)b * N + i0 + i) * XW + F + k * F + warp_n * WN;
#pragma unroll
            for (int tn = 0; tn < TN; ++tn) {
                float2 o;
                o.x = acc[tm][tn][half * 2 + 0];
                o.y = acc[tm][tn][half * 2 + 1];
                *reinterpret_cast<float2*>(xr + tn * 8 + 2 * cc) = o;
            }
        }
    }
}

// =================================================================
// tf32 GEMM + tanh + BN + fused 2:1 row pooling (R4 version, reverted)
// =================================================================
template <int NIN>
__global__ __launch_bounds__(256) void gemm_pool(
        const float* __restrict__ A, const float* __restrict__ Wt,
        const float* __restrict__ bias, const float* __restrict__ bng,
        const float* __restrict__ bnb, float* __restrict__ Out,
        int Kd, int Nc) {
    constexpr int BM = 128, BN = 64, BK = 32;
    constexpr int TM = 2, TN = 4;                // warps 4(M) x 2(N)
    __shared__ uint32_t As[BM][BK + 4];
    __shared__ uint32_t Bs[BK][BN + 8];
    const int bm = blockIdx.y * BM, bn = blockIdx.x * BN;
    const int tid = threadIdx.x, wid = tid >> 5, lane = tid & 31;
    const int g = lane >> 2, cc = lane & 3;
    const int warp_m = wid >> 1, warp_n = wid & 1;

    float acc[TM][TN][4];
#pragma unroll
    for (int tm = 0; tm < TM; ++tm)
#pragma unroll
        for (int tn = 0; tn < TN; ++tn)
#pragma unroll
            for (int q = 0; q < 4; ++q) acc[tm][tn][q] = 0.f;

    float4 ra[4], rb[2];
    const int nk = Kd / BK;

    {
#pragma unroll
        for (int s = 0; s < 4; ++s) {
            int idx = tid + s * 256, r = idx >> 3, cq = idx & 7;
            ra[s] = *reinterpret_cast<const float4*>(A + (size_t)(bm + r) * Kd + cq * 4);
        }
#pragma unroll
        for (int s = 0; s < 2; ++s) {
            int idx = tid + s * 256, kr = idx >> 4, cq = idx & 15;
            rb[s] = *reinterpret_cast<const float4*>(Wt + (size_t)kr * Nc + bn + cq * 4);
        }
    }

    for (int kt = 0; kt < nk; ++kt) {
#pragma unroll
        for (int s = 0; s < 4; ++s) {
            int idx = tid + s * 256, r = idx >> 3, cq = idx & 7;
            As[r][cq * 4 + 0] = f2tf(ra[s].x);
            As[r][cq * 4 + 1] = f2tf(ra[s].y);
            As[r][cq * 4 + 2] = f2tf(ra[s].z);
            As[r][cq * 4 + 3] = f2tf(ra[s].w);
        }
#pragma unroll
        for (int s = 0; s < 2; ++s) {
            int idx = tid + s * 256, kr = idx >> 4, cq = idx & 15;
            Bs[kr][cq * 4 + 0] = f2tf(rb[s].x);
            Bs[kr][cq * 4 + 1] = f2tf(rb[s].y);
            Bs[kr][cq * 4 + 2] = f2tf(rb[s].z);
            Bs[kr][cq * 4 + 3] = f2tf(rb[s].w);
        }
        __syncthreads();
        if (kt + 1 < nk) {
            int k0 = (kt + 1) * BK;
#pragma unroll
            for (int s = 0; s < 4; ++s) {
                int idx = tid + s * 256, r = idx >> 3, cq = idx & 7;
                ra[s] = *reinterpret_cast<const float4*>(
                    A + (size_t)(bm + r) * Kd + k0 + cq * 4);
            }
#pragma unroll
            for (int s = 0; s < 2; ++s) {
                int idx = tid + s * 256, kr = idx >> 4, cq = idx & 15;
                rb[s] = *reinterpret_cast<const float4*>(
                    Wt + (size_t)(k0 + kr) * Nc + bn + cq * 4);
            }
        }
#pragma unroll
        for (int ks = 0; ks < 4; ++ks) {
            uint32_t af[TM][4];
#pragma unroll
            for (int tm = 0; tm < TM; ++tm) {
                int r = warp_m * 32 + tm * 16;
                af[tm][0] = As[r + g][ks * 8 + cc];
                af[tm][1] = As[r + g + 8][ks * 8 + cc];
                af[tm][2] = As[r + g][ks * 8 + cc + 4];
                af[tm][3] = As[r + g + 8][ks * 8 + cc + 4];
            }
#pragma unroll
            for (int tn = 0; tn < TN; ++tn) {
                int nb = warp_n * 32 + tn * 8;
                uint32_t b0 = Bs[ks * 8 + cc][nb + g];
                uint32_t b1 = Bs[ks * 8 + cc + 4][nb + g];
#pragma unroll
                for (int tm = 0; tm < TM; ++tm)
                    mma8(acc[tm][tn], af[tm][0], af[tm][1], af[tm][2], af[tm][3], b0, b1);
            }
        }
        __syncthreads();
    }

    const bool wr = ((g & 1) == 0);
#pragma unroll
    for (int tm = 0; tm < TM; ++tm) {
#pragma unroll
        for (int half = 0; half < 2; ++half) {
            int r = bm + warp_m * 32 + tm * 16 + g + half * 8;
#pragma unroll
            for (int tn = 0; tn < TN; ++tn) {
                int col = bn + warp_n * 32 + tn * 8 + 2 * cc;
                float h0 = bng[col] * tanhf(acc[tm][tn][half * 2 + 0] + bias[col]) + bnb[col];
                float h1 = bng[col + 1] * tanhf(acc[tm][tn][half * 2 + 1] + bias[col + 1]) + bnb[col + 1];
                float p0 = 0.5f * (h0 + __shfl_down_sync(0xffffffffu, h0, 4));
                float p1 = 0.5f * (h1 + __shfl_down_sync(0xffffffffu, h1, 4));
                if (wr) {
                    int pr = (r / NIN) * (NIN / 2) + (r % NIN) / 2;
                    *reinterpret_cast<float2*>(Out + (size_t)pr * Nc + col) =
                        make_float2(p0, p1);
                }
            }
        }
    }
}

// ---------------- coord pooling (tiny) ----------------
__global__ void poolC_kernel(const float* __restrict__ C, float* __restrict__ C1) {
    int idx = blockIdx.x * blockDim.x + threadIdx.x;
    if (idx >= BB * N1 * 3) return;
    int c = idx % 3;
    int i = (idx / 3) % N1;
    int b = idx / (3 * N1);
    size_t base = ((size_t)b * N0 + 2 * i) * 3 + c;
    C1[idx] = 0.5f * (C[base] + C[base + 3]);
}

// ---------------- FC: split-K partials (fp32, deterministic) ----------------
__global__ __launch_bounds__(128) void fc_partial(const float* __restrict__ Flat,
                                                  const float* __restrict__ W) {
    constexpr int KCH = FLATD / 128;   // 256
    const int kb = blockIdx.x * KCH;
    const int tid = threadIdx.x;
    __shared__ float sF[BB][KCH];
    for (int t = tid; t < BB * KCH / 4; t += 128) {
        int b = t / (KCH / 4), kq = t % (KCH / 4);
        *reinterpret_cast<float4*>(&sF[b][kq * 4]) =
            *reinterpret_cast<const float4*>(Flat + (size_t)b * FLATD + kb + kq * 4);
    }
    __syncthreads();

    float4 acc[BB];
#pragma unroll
    for (int b = 0; b < BB; ++b) acc[b] = make_float4(0.f, 0.f, 0.f, 0.f);

    const float* wp = W + (size_t)kb * FC_OUT + tid * 4;
    for (int k = 0; k < KCH; k += 4) {
        float4 w0 = *reinterpret_cast<const float4*>(wp + (size_t)(k + 0) * FC_OUT);
        float4 w1 = *reinterpret_cast<const float4*>(wp + (size_t)(k + 1) * FC_OUT);
        float4 w2 = *reinterpret_cast<const float4*>(wp + (size_t)(k + 2) * FC_OUT);
        float4 w3 = *reinterpret_cast<const float4*>(wp + (size_t)(k + 3) * FC_OUT);
#pragma unroll
        for (int b = 0; b < BB; ++b) {
            float4 f = *reinterpret_cast<float4*>(&sF[b][k]);
            acc[b].x += f.x * w0.x + f.y * w1.x + f.z * w2.x + f.w * w3.x;
            acc[b].y += f.x * w0.y + f.y * w1.y + f.z * w2.y + f.w * w3.y;
            acc[b].z += f.x * w0.z + f.y * w1.z + f.z * w2.z + f.w * w3.z;
            acc[b].w += f.x * w0.w + f.y * w1.w + f.z * w2.w + f.w * w3.w;
        }
    }
#pragma unroll
    for (int b = 0; b < BB; ++b)
        *reinterpret_cast<float4*>(&g_part[blockIdx.x][b * FC_OUT + tid * 4]) = acc[b];
}

__global__ void fc_finalize(const float* __restrict__ fcb, float* __restrict__ out) {
    int idx = blockIdx.x * blockDim.x + threadIdx.x;
    if (idx >= BB * FC_OUT) return;
    int col = idx & (FC_OUT - 1);
    float s = fcb[col];
#pragma unroll
    for (int t = 0; t < 128; ++t) s += g_part[t][idx];
    out[idx] = 1.f / (1.f + __expf(-s));
}

// ---------------- launch ----------------
extern "C" void kernel_launch(void* const* d_in, const int* in_sizes, int n_in,
                              void* d_out, int out_size) {
    const float* V    = (const float*)d_in[0];
    const float* C    = (const float*)d_in[1];
    const float* gkw0 = (const float*)d_in[2];
    const float* gkb0 = (const float*)d_in[3];
    const float* acw0 = (const float*)d_in[4];
    const float* acb0 = (const float*)d_in[5];
    const float* gcw0 = (const float*)d_in[6];
    const float* gcb0 = (const float*)d_in[7];
    const float* bng0 = (const float*)d_in[8];
    const float* bnb0 = (const float*)d_in[9];
    const float* gkw1 = (const float*)d_in[10];
    const float* gkb1 = (const float*)d_in[11];
    const float* acw1 = (const float*)d_in[12];
    const float* acb1 = (const float*)d_in[13];
    const float* gcw1 = (const float*)d_in[14];
    const float* gcb1 = (const float*)d_in[15];
    const float* bng1 = (const float*)d_in[16];
    const float* bnb1 = (const float*)d_in[17];
    const float* fcw  = (const float*)d_in[18];
    const float* fcb  = (const float*)d_in[19];
    float* out = (float*)d_out;

    float *X0, *H0p, *C1, *X1, *Flat;
    cudaGetSymbolAddress((void**)&X0, g_X0);
    cudaGetSymbolAddress((void**)&H0p, g_H0p);
    cudaGetSymbolAddress((void**)&C1, g_C1);
    cudaGetSymbolAddress((void**)&X1, g_X1);
    cudaGetSymbolAddress((void**)&Flat, g_Flat);

    const int smsg0 = (int)sizeof(MsgSmem<F0c>);
    const int smsg1 = (int)sizeof(MsgSmem<F1c>);
    cudaFuncSetAttribute(msg_kernel<F0c, N0>,
                         cudaFuncAttributeMaxDynamicSharedMemorySize, smsg0);
    cudaFuncSetAttribute(msg_kernel<F1c, N1>,
                         cudaFuncAttributeMaxDynamicSharedMemorySize, smsg1);

    // layer 0
    msg_kernel<F0c, N0><<<dim3(N0 / 16, BB), 256, smsg0>>>(
        V, C, gkw0, gkb0, acw0, acb0, X0);
    gemm_pool<N0><<<dim3(F1c / 64, BB * N0 / 128), 256>>>(
        X0, gcw0, gcb0, bng0, bnb0, H0p, (KK + 1) * F0c, F1c);
    poolC_kernel<<<(BB * N1 * 3 + 255) / 256, 256>>>(C, C1);

    // layer 1
    msg_kernel<F1c, N1><<<dim3(N1 / 16, BB), 256, smsg1>>>(
        H0p, C1, gkw1, gkb1, acw1, acb1, X1);
    gemm_pool<N1><<<dim3(F2c / 64, BB * N1 / 128), 256>>>(
        X1, gcw1, gcb1, bng1, bnb1, Flat, (KK + 1) * F1c, F2c);

    // FC head (fp32)
    fc_partial<<<128, 128>>>(Flat, fcw);
    fc_finalize<<<(BB * FC_OUT + 255) / 256, 256>>>(fcb, out);
}

// round 7
// speedup vs baseline: 1.0722x; 1.0722x over previous
#include <cuda_runtime.h>
#include <cstdint>

// ---------------- model constants ----------------
#define BB 16
#define N0 512
#define N1 256
#define N2 128
#define F0c 64
#define F1c 128
#define F2c 256
#define KK 8
#define FC_OUT 512
#define FLATD (N2 * F2c)        // 32768
#define EPSC 1e-9f
#define ZCUT 18.0f              // exp(-z) below e^-18 ~ 1.5e-8: negligible vs 1e-3 tol

// ---------------- scratch (device globals, no allocs) ----------------
__device__ float g_X0[BB * N0 * (F0c + KK * F0c)];   // [8192, 576]
__device__ float g_H0p[BB * N1 * F1c];
__device__ float g_C1[BB * N1 * 3];
__device__ float g_X1[BB * N1 * (F1c + KK * F1c)];   // [4096, 1152]
__device__ float g_Flat[BB * N2 * F2c];
__device__ float g_part[128][BB * FC_OUT];

// ---------------- tf32 helpers ----------------
__device__ __forceinline__ uint32_t f2tf(float x) {
    uint32_t r;
    asm("cvt.rna.tf32.f32 %0, %1;" : "=r"(r) : "f"(x));
    return r;
}
__device__ __forceinline__ void mma8(float* c,
        uint32_t a0, uint32_t a1, uint32_t a2, uint32_t a3,
        uint32_t b0, uint32_t b1) {
    asm volatile(
        "mma.sync.aligned.m16n8k8.row.col.f32.tf32.tf32.f32 "
        "{%0,%1,%2,%3},{%4,%5,%6,%7},{%8,%9},{%0,%1,%2,%3};"
        : "+f"(c[0]), "+f"(c[1]), "+f"(c[2]), "+f"(c[3])
        : "r"(a0), "r"(a1), "r"(a2), "r"(a3), "r"(b0), "r"(b1));
}

// =================================================================
// Fused message passing: tf32 mma, exp-sparsified A build,
// single-barrier pipeline, COLUMN-balanced per-warp build.
// =================================================================
template <int F>
struct MsgSmem {
    float4 Ci[16];
    float  Rni[16];
    float  U[16][KK];
    float  W[16][KK];
    float  Umin[16];
    uint32_t A[2][128][36];
    uint32_t Vt[2][32][F + 8];
    unsigned short wIdx[8][64];
    float  wD2[8][64];
    float  wCs[8][64];
};

template <int F, int N>
__global__ __launch_bounds__(256, (F == 64) ? 3 : 2) void msg_kernel(
        const float* __restrict__ V, const float* __restrict__ C,
        const float* __restrict__ gkw, const float* __restrict__ gkb,
        const float* __restrict__ acw, const float* __restrict__ acb,
        float* __restrict__ X) {
    constexpr int TI = 16, TJ = 32, XW = F + KK * F;
    constexpr int WARPS_M = (F == 128) ? 2 : 4;
    constexpr int WARPS_N = 8 / WARPS_M;
    constexpr int WM = 128 / WARPS_M;
    constexpr int WN = F / WARPS_N;         // 32
    constexpr int TM = WM / 16;
    constexpr int TN = WN / 8;              // 4
    constexpr int VLD = TJ * (F / 4) / 256; // float4 per thread per V tile
    constexpr int T = N / TJ;

    extern __shared__ char smem_raw[];
    auto& S = *reinterpret_cast<MsgSmem<F>*>(smem_raw);

    const int b = blockIdx.y;
    const int i0 = blockIdx.x * TI;
    const int tid = threadIdx.x;
    const int wid = tid >> 5, lane = tid & 31;
    const int g = lane >> 2, cc = lane & 3;
    const int warp_m = wid / WARPS_N, warp_n = wid % WARPS_N;
    const int bi = lane & 15;                  // build: row index
    const int bjh = lane >> 4;                 // build: col sub-offset (0/1)

    // ---- setup ----
    if (tid < TI) {
        int i = i0 + tid;
        float x = C[((size_t)b * N + i) * 3 + 0];
        float y = C[((size_t)b * N + i) * 3 + 1];
        float z = C[((size_t)b * N + i) * 3 + 2];
        float l2 = x * x + y * y + z * z;
        S.Ci[tid] = make_float4(x, y, z, l2);
        S.Rni[tid] = rsqrtf(l2 + EPSC);
    }
    {   // fused gates: 256 threads = 2 gates x 16 rows x 8 k
        int gate = tid >> 7;
        int r = (tid >> 3) & (TI - 1);
        int k = tid & 7;
        const float* wgt = gate ? acw : gkw;
        float s = gate ? acb[k] : gkb[k];
        const float* vrow = V + ((size_t)b * N + i0 + r) * F;
#pragma unroll 8
        for (int f = 0; f < F; ++f) s += vrow[f] * wgt[f * KK + k];
        if (gate) {
            S.W[r][k] = 1.f / (1.f + __expf(-s));
        } else {
            float u = fmaxf(s, 0.f) + log1pf(__expf(-fabsf(s)));
            S.U[r][k] = u;
            float um = u;
            um = fminf(um, __shfl_xor_sync(0xffffffffu, um, 1));
            um = fminf(um, __shfl_xor_sync(0xffffffffu, um, 2));
            um = fminf(um, __shfl_xor_sync(0xffffffffu, um, 4));
            if (k == 0) S.Umin[r] = um;
        }
    }
    // copy V rows into first F cols of X
    for (int t = tid; t < TI * (F / 4); t += 256) {
        int i = t / (F / 4), fq = t % (F / 4);
        float4 vv = reinterpret_cast<const float4*>(V + ((size_t)b * N + i0 + i) * F)[fq];
        reinterpret_cast<float4*>(X + ((size_t)b * N + i0 + i) * XW)[fq] = vv;
    }
    __syncthreads();   // gates/Ci visible

    // ---- column-balanced per-warp A-tile builder ----
    // warp w owns cols {2w+bjh, 16+2w+bjh} x all 16 rows (rows spread over lanes).
    auto build = [&](int buf, const float* cxa, const float* cya, const float* cza) {
        int wcnt = 0;
#pragma unroll
        for (int s = 0; s < 2; ++s) {
            int i = bi;
            int jj = s * 16 + wid * 2 + bjh;
            float cx = cxa[s], cy = cya[s], cz = cza[s];
            float l2 = cx * cx + cy * cy + cz * cz;
            float4 ci = S.Ci[i];
            float dot = ci.x * cx + ci.y * cy + ci.z * cz;
            float d2 = fabsf(ci.w + l2 - 2.f * dot) + EPSC;
            bool near = (d2 * S.Umin[i] <= ZCUT);
            if (!near) {
#pragma unroll
                for (int k = 0; k < KK; ++k) S.A[buf][(k << 4) | i][jj] = 0u;
            }
            unsigned mask = __ballot_sync(0xffffffffu, near);
            if (near) {
                int slot = wcnt + __popc(mask & ((1u << lane) - 1u));
                S.wIdx[wid][slot] = (unsigned short)((i << 5) | jj);
                S.wD2[wid][slot] = d2;
                S.wCs[wid][slot] = dot * S.Rni[i] * rsqrtf(l2 + EPSC);
            }
            wcnt += __popc(mask);
        }
        __syncwarp();
        const int work = wcnt * KK;
        for (int t = lane; t < work; t += 32) {
            int e = t >> 3, k = t & 7;
            int p = S.wIdx[wid][e];
            int i = p >> 5, jj = p & 31;
            float d2 = S.wD2[wid][e], cs = S.wCs[wid][e];
            float u = S.U[i][k], w = S.W[i][k];
            float z = d2 * u;
            float ex = (z > ZCUT) ? 0.f : __expf(-z);
            S.A[buf][(k << 4) | i][jj] = f2tf(ex * (w * cs + 1.f - w));
        }
    };

    // stage tile 0 + build(0)
    {
#pragma unroll
        for (int s = 0; s < VLD; ++s) {
            int idx = tid + s * 256;
            int j = idx / (F / 4), fq = idx % (F / 4);
            float4 vv = reinterpret_cast<const float4*>(V + ((size_t)b * N + j) * F)[fq];
            S.Vt[0][j][fq * 4 + 0] = f2tf(vv.x);
            S.Vt[0][j][fq * 4 + 1] = f2tf(vv.y);
            S.Vt[0][j][fq * 4 + 2] = f2tf(vv.z);
            S.Vt[0][j][fq * 4 + 3] = f2tf(vv.w);
        }
        float cxa[2], cya[2], cza[2];
#pragma unroll
        for (int s = 0; s < 2; ++s) {
            int jj = s * 16 + wid * 2 + bjh;
            const float* cp = C + ((size_t)b * N + jj) * 3;
            cxa[s] = cp[0]; cya[s] = cp[1]; cza[s] = cp[2];
        }
        build(0, cxa, cya, cza);
    }
    __syncthreads();

    float acc[TM][TN][4];
#pragma unroll
    for (int tm = 0; tm < TM; ++tm)
#pragma unroll
        for (int tn = 0; tn < TN; ++tn)
#pragma unroll
            for (int q = 0; q < 4; ++q) acc[tm][tn][q] = 0.f;

    for (int t = 0; t < T; ++t) {
        const int cur = t & 1, nxt = cur ^ 1;
        const bool more = (t + 1 < T);
        // prefetch tile t+1 (V tile + this lane's build-column coords)
        float4 vreg[VLD];
        float cxa[2] = {0.f, 0.f}, cya[2] = {0.f, 0.f}, cza[2] = {0.f, 0.f};
        if (more) {
            int j0n = (t + 1) * TJ;
#pragma unroll
            for (int s = 0; s < VLD; ++s) {
                int idx = tid + s * 256;
                int j = idx / (F / 4), fq = idx % (F / 4);
                vreg[s] = reinterpret_cast<const float4*>(
                    V + ((size_t)b * N + j0n + j) * F)[fq];
            }
#pragma unroll
            for (int s = 0; s < 2; ++s) {
                int jj = s * 16 + wid * 2 + bjh;
                const float* cp = C + ((size_t)b * N + j0n + jj) * 3;
                cxa[s] = cp[0]; cya[s] = cp[1]; cza[s] = cp[2];
            }
        }
        // mma on tile t
#pragma unroll
        for (int ks = 0; ks < 4; ++ks) {
            uint32_t af[TM][4];
#pragma unroll
            for (int tm = 0; tm < TM; ++tm) {
                int r = warp_m * WM + tm * 16;
                af[tm][0] = S.A[cur][r + g][ks * 8 + cc];
                af[tm][1] = S.A[cur][r + g + 8][ks * 8 + cc];
                af[tm][2] = S.A[cur][r + g][ks * 8 + cc + 4];
                af[tm][3] = S.A[cur][r + g + 8][ks * 8 + cc + 4];
            }
#pragma unroll
            for (int tn = 0; tn < TN; ++tn) {
                int nb = warp_n * WN + tn * 8;
                uint32_t b0 = S.Vt[cur][ks * 8 + cc][nb + g];
                uint32_t b1 = S.Vt[cur][ks * 8 + cc + 4][nb + g];
#pragma unroll
                for (int tm = 0; tm < TM; ++tm)
                    mma8(acc[tm][tn], af[tm][0], af[tm][1], af[tm][2], af[tm][3], b0, b1);
            }
        }
        // stage + build tile t+1 (no cross-warp deps)
        if (more) {
#pragma unroll
            for (int s = 0; s < VLD; ++s) {
                int idx = tid + s * 256;
                int j = idx / (F / 4), fq = idx % (F / 4);
                S.Vt[nxt][j][fq * 4 + 0] = f2tf(vreg[s].x);
                S.Vt[nxt][j][fq * 4 + 1] = f2tf(vreg[s].y);
                S.Vt[nxt][j][fq * 4 + 2] = f2tf(vreg[s].z);
                S.Vt[nxt][j][fq * 4 + 3] = f2tf(vreg[s].w);
            }
            build(nxt, cxa, cya, cza);
        }
        __syncthreads();   // single barrier per tile
    }

    // write M section of X: row m = k*16+i
#pragma unroll
    for (int tm = 0; tm < TM; ++tm) {
#pragma unroll
        for (int half = 0; half < 2; ++half) {
            int m = warp_m * WM + tm * 16 + g + half * 8;
            int k = m >> 4, i = m & 15;
            float* xr = X + ((size_t)b * N + i0 + i) * XW + F + k * F + warp_n * WN;
#pragma unroll
            for (int tn = 0; tn < TN; ++tn) {
                float2 o;
                o.x = acc[tm][tn][half * 2 + 0];
                o.y = acc[tm][tn][half * 2 + 1];
                *reinterpret_cast<float2*>(xr + tn * 8 + 2 * cc) = o;
            }
        }
    }
}

// =================================================================
// tf32 GEMM + tanh + BN + fused 2:1 row pooling (R4 version)
// =================================================================
template <int NIN>
__global__ __launch_bounds__(256) void gemm_pool(
        const float* __restrict__ A, const float* __restrict__ Wt,
        const float* __restrict__ bias, const float* __restrict__ bng,
        const float* __restrict__ bnb, float* __restrict__ Out,
        int Kd, int Nc) {
    constexpr int BM = 128, BN = 64, BK = 32;
    constexpr int TM = 2, TN = 4;                // warps 4(M) x 2(N)
    __shared__ uint32_t As[BM][BK + 4];
    __shared__ uint32_t Bs[BK][BN + 8];
    const int bm = blockIdx.y * BM, bn = blockIdx.x * BN;
    const int tid = threadIdx.x, wid = tid >> 5, lane = tid & 31;
    const int g = lane >> 2, cc = lane & 3;
    const int warp_m = wid >> 1, warp_n = wid & 1;

    float acc[TM][TN][4];
#pragma unroll
    for (int tm = 0; tm < TM; ++tm)
#pragma unroll
        for (int tn = 0; tn < TN; ++tn)
#pragma unroll
            for (int q = 0; q < 4; ++q) acc[tm][tn][q] = 0.f;

    float4 ra[4], rb[2];
    const int nk = Kd / BK;

    {
#pragma unroll
        for (int s = 0; s < 4; ++s) {
            int idx = tid + s * 256, r = idx >> 3, cq = idx & 7;
            ra[s] = *reinterpret_cast<const float4*>(A + (size_t)(bm + r) * Kd + cq * 4);
        }
#pragma unroll
        for (int s = 0; s < 2; ++s) {
            int idx = tid + s * 256, kr = idx >> 4, cq = idx & 15;
            rb[s] = *reinterpret_cast<const float4*>(Wt + (size_t)kr * Nc + bn + cq * 4);
        }
    }

    for (int kt = 0; kt < nk; ++kt) {
#pragma unroll
        for (int s = 0; s < 4; ++s) {
            int idx = tid + s * 256, r = idx >> 3, cq = idx & 7;
            As[r][cq * 4 + 0] = f2tf(ra[s].x);
            As[r][cq * 4 + 1] = f2tf(ra[s].y);
            As[r][cq * 4 + 2] = f2tf(ra[s].z);
            As[r][cq * 4 + 3] = f2tf(ra[s].w);
        }
#pragma unroll
        for (int s = 0; s < 2; ++s) {
            int idx = tid + s * 256, kr = idx >> 4, cq = idx & 15;
            Bs[kr][cq * 4 + 0] = f2tf(rb[s].x);
            Bs[kr][cq * 4 + 1] = f2tf(rb[s].y);
            Bs[kr][cq * 4 + 2] = f2tf(rb[s].z);
            Bs[kr][cq * 4 + 3] = f2tf(rb[s].w);
        }
        __syncthreads();
        if (kt + 1 < nk) {
            int k0 = (kt + 1) * BK;
#pragma unroll
            for (int s = 0; s < 4; ++s) {
                int idx = tid + s * 256, r = idx >> 3, cq = idx & 7;
                ra[s] = *reinterpret_cast<const float4*>(
                    A + (size_t)(bm + r) * Kd + k0 + cq * 4);
            }
#pragma unroll
            for (int s = 0; s < 2; ++s) {
                int idx = tid + s * 256, kr = idx >> 4, cq = idx & 15;
                rb[s] = *reinterpret_cast<const float4*>(
                    Wt + (size_t)(k0 + kr) * Nc + bn + cq * 4);
            }
        }
#pragma unroll
        for (int ks = 0; ks < 4; ++ks) {
            uint32_t af[TM][4];
#pragma unroll
            for (int tm = 0; tm < TM; ++tm) {
                int r = warp_m * 32 + tm * 16;
                af[tm][0] = As[r + g][ks * 8 + cc];
                af[tm][1] = As[r + g + 8][ks * 8 + cc];
                af[tm][2] = As[r + g][ks * 8 + cc + 4];
                af[tm][3] = As[r + g + 8][ks * 8 + cc + 4];
            }
#pragma unroll
            for (int tn = 0; tn < TN; ++tn) {
                int nb = warp_n * 32 + tn * 8;
                uint32_t b0 = Bs[ks * 8 + cc][nb + g];
                uint32_t b1 = Bs[ks * 8 + cc + 4][nb + g];
#pragma unroll
                for (int tm = 0; tm < TM; ++tm)
                    mma8(acc[tm][tn], af[tm][0], af[tm][1], af[tm][2], af[tm][3], b0, b1);
            }
        }
        __syncthreads();
    }

    const bool wr = ((g & 1) == 0);
#pragma unroll
    for (int tm = 0; tm < TM; ++tm) {
#pragma unroll
        for (int half = 0; half < 2; ++half) {
            int r = bm + warp_m * 32 + tm * 16 + g + half * 8;
#pragma unroll
            for (int tn = 0; tn < TN; ++tn) {
                int col = bn + warp_n * 32 + tn * 8 + 2 * cc;
                float h0 = bng[col] * tanhf(acc[tm][tn][half * 2 + 0] + bias[col]) + bnb[col];
                float h1 = bng[col + 1] * tanhf(acc[tm][tn][half * 2 + 1] + bias[col + 1]) + bnb[col + 1];
                float p0 = 0.5f * (h0 + __shfl_down_sync(0xffffffffu, h0, 4));
                float p1 = 0.5f * (h1 + __shfl_down_sync(0xffffffffu, h1, 4));
                if (wr) {
                    int pr = (r / NIN) * (NIN / 2) + (r % NIN) / 2;
                    *reinterpret_cast<float2*>(Out + (size_t)pr * Nc + col) =
                        make_float2(p0, p1);
                }
            }
        }
    }
}

// ---------------- coord pooling (tiny) ----------------
__global__ void poolC_kernel(const float* __restrict__ C, float* __restrict__ C1) {
    int idx = blockIdx.x * blockDim.x + threadIdx.x;
    if (idx >= BB * N1 * 3) return;
    int c = idx % 3;
    int i = (idx / 3) % N1;
    int b = idx / (3 * N1);
    size_t base = ((size_t)b * N0 + 2 * i) * 3 + c;
    C1[idx] = 0.5f * (C[base] + C[base + 3]);
}

// ---------------- FC: split-K partials (fp32, deterministic) ----------------
__global__ __launch_bounds__(128) void fc_partial(const float* __restrict__ Flat,
                                                  const float* __restrict__ W) {
    constexpr int KCH = FLATD / 128;   // 256
    const int kb = blockIdx.x * KCH;
    const int tid = threadIdx.x;
    __shared__ float sF[BB][KCH];
    for (int t = tid; t < BB * KCH / 4; t += 128) {
        int b = t / (KCH / 4), kq = t % (KCH / 4);
        *reinterpret_cast<float4*>(&sF[b][kq * 4]) =
            *reinterpret_cast<const float4*>(Flat + (size_t)b * FLATD + kb + kq * 4);
    }
    __syncthreads();

    float4 acc[BB];
#pragma unroll
    for (int b = 0; b < BB; ++b) acc[b] = make_float4(0.f, 0.f, 0.f, 0.f);

    const float* wp = W + (size_t)kb * FC_OUT + tid * 4;
    for (int k = 0; k < KCH; k += 4) {
        float4 w0 = *reinterpret_cast<const float4*>(wp + (size_t)(k + 0) * FC_OUT);
        float4 w1 = *reinterpret_cast<const float4*>(wp + (size_t)(k + 1) * FC_OUT);
        float4 w2 = *reinterpret_cast<const float4*>(wp + (size_t)(k + 2) * FC_OUT);
        float4 w3 = *reinterpret_cast<const float4*>(wp + (size_t)(k + 3) * FC_OUT);
#pragma unroll
        for (int b = 0; b < BB; ++b) {
            float4 f = *reinterpret_cast<float4*>(&sF[b][k]);
            acc[b].x += f.x * w0.x + f.y * w1.x + f.z * w2.x + f.w * w3.x;
            acc[b].y += f.x * w0.y + f.y * w1.y + f.z * w2.y + f.w * w3.y;
            acc[b].z += f.x * w0.z + f.y * w1.z + f.z * w2.z + f.w * w3.z;
            acc[b].w += f.x * w0.w + f.y * w1.w + f.z * w2.w + f.w * w3.w;
        }
    }
#pragma unroll
    for (int b = 0; b < BB; ++b)
        *reinterpret_cast<float4*>(&g_part[blockIdx.x][b * FC_OUT + tid * 4]) = acc[b];
}

__global__ void fc_finalize(const float* __restrict__ fcb, float* __restrict__ out) {
    int idx = blockIdx.x * blockDim.x + threadIdx.x;
    if (idx >= BB * FC_OUT) return;
    int col = idx & (FC_OUT - 1);
    float s = fcb[col];
#pragma unroll
    for (int t = 0; t < 128; ++t) s += g_part[t][idx];
    out[idx] = 1.f / (1.f + __expf(-s));
}

// ---------------- launch ----------------
extern "C" void kernel_launch(void* const* d_in, const int* in_sizes, int n_in,
                              void* d_out, int out_size) {
    const float* V    = (const float*)d_in[0];
    const float* C    = (const float*)d_in[1];
    const float* gkw0 = (const float*)d_in[2];
    const float* gkb0 = (const float*)d_in[3];
    const float* acw0 = (const float*)d_in[4];
    const float* acb0 = (const float*)d_in[5];
    const float* gcw0 = (const float*)d_in[6];
    const float* gcb0 = (const float*)d_in[7];
    const float* bng0 = (const float*)d_in[8];
    const float* bnb0 = (const float*)d_in[9];
    const float* gkw1 = (const float*)d_in[10];
    const float* gkb1 = (const float*)d_in[11];
    const float* acw1 = (const float*)d_in[12];
    const float* acb1 = (const float*)d_in[13];
    const float* gcw1 = (const float*)d_in[14];
    const float* gcb1 = (const float*)d_in[15];
    const float* bng1 = (const float*)d_in[16];
    const float* bnb1 = (const float*)d_in[17];
    const float* fcw  = (const float*)d_in[18];
    const float* fcb  = (const float*)d_in[19];
    float* out = (float*)d_out;

    float *X0, *H0p, *C1, *X1, *Flat;
    cudaGetSymbolAddress((void**)&X0, g_X0);
    cudaGetSymbolAddress((void**)&H0p, g_H0p);
    cudaGetSymbolAddress((void**)&C1, g_C1);
    cudaGetSymbolAddress((void**)&X1, g_X1);
    cudaGetSymbolAddress((void**)&Flat, g_Flat);

    const int smsg0 = (int)sizeof(MsgSmem<F0c>);
    const int smsg1 = (int)sizeof(MsgSmem<F1c>);
    cudaFuncSetAttribute(msg_kernel<F0c, N0>,
                         cudaFuncAttributeMaxDynamicSharedMemorySize, smsg0);
    cudaFuncSetAttribute(msg_kernel<F1c, N1>,
                         cudaFuncAttributeMaxDynamicSharedMemorySize, smsg1);

    // layer 0
    msg_kernel<F0c, N0><<<dim3(N0 / 16, BB), 256, smsg0>>>(
        V, C, gkw0, gkb0, acw0, acb0, X0);
    gemm_pool<N0><<<dim3(F1c / 64, BB * N0 / 128), 256>>>(
        X0, gcw0, gcb0, bng0, bnb0, H0p, (KK + 1) * F0c, F1c);
    poolC_kernel<<<(BB * N1 * 3 + 255) / 256, 256>>>(C, C1);

    // layer 1
    msg_kernel<F1c, N1><<<dim3(N1 / 16, BB), 256, smsg1>>>(
        H0p, C1, gkw1, gkb1, acw1, acb1, X1);
    gemm_pool<N1><<<dim3(F2c / 64, BB * N1 / 128), 256>>>(
        X1, gcw1, gcb1, bng1, bnb1, Flat, (KK + 1) * F1c, F2c);

    // FC head (fp32)
    fc_partial<<<128, 128>>>(Flat, fcw);
    fc_finalize<<<(BB * FC_OUT + 255) / 256, 256>>>(fcb, out);
}

// round 8
// speedup vs baseline: 1.1203x; 1.0449x over previous
#include <cuda_runtime.h>
#include <cstdint>

// ---------------- model constants ----------------
#define BB 16
#define N0 512
#define N1 256
#define N2 128
#define F0c 64
#define F1c 128
#define F2c 256
#define KK 8
#define FC_OUT 512
#define FLATD (N2 * F2c)        // 32768
#define EPSC 1e-9f
#define ZCUT 18.0f              // exp(-z) below e^-18 ~ 1.5e-8: negligible vs 1e-3 tol

// ---------------- scratch (device globals, no allocs) ----------------
__device__ float g_X0[BB * N0 * (F0c + KK * F0c)];   // [8192, 576]
__device__ float g_H0p[BB * N1 * F1c];
__device__ float g_C1[BB * N1 * 3];
__device__ float g_X1[BB * N1 * (F1c + KK * F1c)];   // [4096, 1152]
__device__ float g_Flat[BB * N2 * F2c];
__device__ float g_part[128][BB * FC_OUT];

// ---------------- tf32 helpers ----------------
__device__ __forceinline__ uint32_t f2tf(float x) {
    uint32_t r;
    asm("cvt.rna.tf32.f32 %0, %1;" : "=r"(r) : "f"(x));
    return r;
}
__device__ __forceinline__ void mma8(float* c,
        uint32_t a0, uint32_t a1, uint32_t a2, uint32_t a3,
        uint32_t b0, uint32_t b1) {
    asm volatile(
        "mma.sync.aligned.m16n8k8.row.col.f32.tf32.tf32.f32 "
        "{%0,%1,%2,%3},{%4,%5,%6,%7},{%8,%9},{%0,%1,%2,%3};"
        : "+f"(c[0]), "+f"(c[1]), "+f"(c[2]), "+f"(c[3])
        : "r"(a0), "r"(a1), "r"(a2), "r"(a3), "r"(b0), "r"(b1));
}

// =================================================================
// Fused message passing: tf32 mma, exp-sparsified A build,
// single-barrier pipeline, column-balanced build, TRANSPOSED A tile
// (AT[j][m], m = i*8+k) so per-pair k-vectors are contiguous -> STS.128.
// =================================================================
template <int F>
struct MsgSmem {
    float4 Ci[16];
    float  Rni[16];
    float  U[16][KK];     // rows 32B-aligned -> float4 loads of k-quads OK
    float  W[16][KK];
    float  Umin[16];
    uint32_t A[2][32][136];        // AT: [j][m=i*8+k], pitch 136 (8 mod 32 -> cf frags)
    uint32_t Vt[2][32][F + 8];
    unsigned short wIdx[8][64];
    float  wD2[8][64];
    float  wCs[8][64];
};

template <int F, int N>
__global__ __launch_bounds__(256, (F == 64) ? 3 : 2) void msg_kernel(
        const float* __restrict__ V, const float* __restrict__ C,
        const float* __restrict__ gkw, const float* __restrict__ gkb,
        const float* __restrict__ acw, const float* __restrict__ acb,
        float* __restrict__ X) {
    constexpr int TI = 16, TJ = 32, XW = F + KK * F;
    constexpr int WARPS_M = (F == 128) ? 2 : 4;
    constexpr int WARPS_N = 8 / WARPS_M;
    constexpr int WM = 128 / WARPS_M;
    constexpr int WN = F / WARPS_N;         // 32
    constexpr int TM = WM / 16;
    constexpr int TN = WN / 8;              // 4
    constexpr int VLD = TJ * (F / 4) / 256; // float4 per thread per V tile
    constexpr int T = N / TJ;

    extern __shared__ char smem_raw[];
    auto& S = *reinterpret_cast<MsgSmem<F>*>(smem_raw);

    const int b = blockIdx.y;
    const int i0 = blockIdx.x * TI;
    const int tid = threadIdx.x;
    const int wid = tid >> 5, lane = tid & 31;
    const int g = lane >> 2, cc = lane & 3;
    const int warp_m = wid / WARPS_N, warp_n = wid % WARPS_N;
    const int bi = lane & 15;                  // build: row index
    const int bjh = lane >> 4;                 // build: col sub-offset (0/1)

    // ---- setup ----
    if (tid < TI) {
        int i = i0 + tid;
        float x = C[((size_t)b * N + i) * 3 + 0];
        float y = C[((size_t)b * N + i) * 3 + 1];
        float z = C[((size_t)b * N + i) * 3 + 2];
        float l2 = x * x + y * y + z * z;
        S.Ci[tid] = make_float4(x, y, z, l2);
        S.Rni[tid] = rsqrtf(l2 + EPSC);
    }
    {   // fused gates: 256 threads = 2 gates x 16 rows x 8 k
        int gate = tid >> 7;
        int r = (tid >> 3) & (TI - 1);
        int k = tid & 7;
        const float* wgt = gate ? acw : gkw;
        float s = gate ? acb[k] : gkb[k];
        const float* vrow = V + ((size_t)b * N + i0 + r) * F;
#pragma unroll 8
        for (int f = 0; f < F; ++f) s += vrow[f] * wgt[f * KK + k];
        if (gate) {
            S.W[r][k] = 1.f / (1.f + __expf(-s));
        } else {
            float u = fmaxf(s, 0.f) + log1pf(__expf(-fabsf(s)));
            S.U[r][k] = u;
            float um = u;
            um = fminf(um, __shfl_xor_sync(0xffffffffu, um, 1));
            um = fminf(um, __shfl_xor_sync(0xffffffffu, um, 2));
            um = fminf(um, __shfl_xor_sync(0xffffffffu, um, 4));
            if (k == 0) S.Umin[r] = um;
        }
    }
    // copy V rows into first F cols of X
    for (int t = tid; t < TI * (F / 4); t += 256) {
        int i = t / (F / 4), fq = t % (F / 4);
        float4 vv = reinterpret_cast<const float4*>(V + ((size_t)b * N + i0 + i) * F)[fq];
        reinterpret_cast<float4*>(X + ((size_t)b * N + i0 + i) * XW)[fq] = vv;
    }
    __syncthreads();   // gates/Ci visible

    // ---- column-balanced per-warp A-tile builder (transposed AT) ----
    // warp w owns cols {2w+bjh, 16+2w+bjh} x all 16 rows.
    // AT[jj][i*8+k]: 8 k-entries of a pair are contiguous -> STS.128.
    auto build = [&](int buf, const float* cxa, const float* cya, const float* cza) {
        int wcnt = 0;
#pragma unroll
        for (int s = 0; s < 2; ++s) {
            int i = bi;
            int jj = s * 16 + wid * 2 + bjh;
            float cx = cxa[s], cy = cya[s], cz = cza[s];
            float l2 = cx * cx + cy * cy + cz * cz;
            float4 ci = S.Ci[i];
            float dot = ci.x * cx + ci.y * cy + ci.z * cz;
            float d2 = fabsf(ci.w + l2 - 2.f * dot) + EPSC;
            bool near = (d2 * S.Umin[i] <= ZCUT);
            if (!near) {
                uint4 z = make_uint4(0u, 0u, 0u, 0u);
                *reinterpret_cast<uint4*>(&S.A[buf][jj][i * 8 + 0]) = z;
                *reinterpret_cast<uint4*>(&S.A[buf][jj][i * 8 + 4]) = z;
            }
            unsigned mask = __ballot_sync(0xffffffffu, near);
            if (near) {
                int slot = wcnt + __popc(mask & ((1u << lane) - 1u));
                S.wIdx[wid][slot] = (unsigned short)((i << 5) | jj);
                S.wD2[wid][slot] = d2;
                S.wCs[wid][slot] = dot * S.Rni[i] * rsqrtf(l2 + EPSC);
            }
            wcnt += __popc(mask);
        }
        __syncwarp();
        // exp phase: thread t -> (entry e, k-quad h); 4 exps + 1 STS.128
        const int work = wcnt * 2;
        for (int t = lane; t < work; t += 32) {
            int e = t >> 1, h = t & 1;
            int p = S.wIdx[wid][e];
            int i = p >> 5, jj = p & 31;
            float d2 = S.wD2[wid][e], cs = S.wCs[wid][e];
            float4 uu = *reinterpret_cast<const float4*>(&S.U[i][h * 4]);
            float4 ww = *reinterpret_cast<const float4*>(&S.W[i][h * 4]);
            uint4 o;
            {
                float z0 = d2 * uu.x;
                float e0 = (z0 > ZCUT) ? 0.f : __expf(-z0);
                o.x = f2tf(e0 * (ww.x * cs + 1.f - ww.x));
            }
            {
                float z1 = d2 * uu.y;
                float e1 = (z1 > ZCUT) ? 0.f : __expf(-z1);
                o.y = f2tf(e1 * (ww.y * cs + 1.f - ww.y));
            }
            {
                float z2 = d2 * uu.z;
                float e2 = (z2 > ZCUT) ? 0.f : __expf(-z2);
                o.z = f2tf(e2 * (ww.z * cs + 1.f - ww.z));
            }
            {
                float z3 = d2 * uu.w;
                float e3 = (z3 > ZCUT) ? 0.f : __expf(-z3);
                o.w = f2tf(e3 * (ww.w * cs + 1.f - ww.w));
            }
            *reinterpret_cast<uint4*>(&S.A[buf][jj][i * 8 + h * 4]) = o;
        }
    };

    // stage tile 0 + build(0)
    {
#pragma unroll
        for (int s = 0; s < VLD; ++s) {
            int idx = tid + s * 256;
            int j = idx / (F / 4), fq = idx % (F / 4);
            float4 vv = reinterpret_cast<const float4*>(V + ((size_t)b * N + j) * F)[fq];
            S.Vt[0][j][fq * 4 + 0] = f2tf(vv.x);
            S.Vt[0][j][fq * 4 + 1] = f2tf(vv.y);
            S.Vt[0][j][fq * 4 + 2] = f2tf(vv.z);
            S.Vt[0][j][fq * 4 + 3] = f2tf(vv.w);
        }
        float cxa[2], cya[2], cza[2];
#pragma unroll
        for (int s = 0; s < 2; ++s) {
            int jj = s * 16 + wid * 2 + bjh;
            const float* cp = C + ((size_t)b * N + jj) * 3;
            cxa[s] = cp[0]; cya[s] = cp[1]; cza[s] = cp[2];
        }
        build(0, cxa, cya, cza);
    }
    __syncthreads();

    float acc[TM][TN][4];
#pragma unroll
    for (int tm = 0; tm < TM; ++tm)
#pragma unroll
        for (int tn = 0; tn < TN; ++tn)
#pragma unroll
            for (int q = 0; q < 4; ++q) acc[tm][tn][q] = 0.f;

    for (int t = 0; t < T; ++t) {
        const int cur = t & 1, nxt = cur ^ 1;
        const bool more = (t + 1 < T);
        // prefetch tile t+1
        float4 vreg[VLD];
        float cxa[2] = {0.f, 0.f}, cya[2] = {0.f, 0.f}, cza[2] = {0.f, 0.f};
        if (more) {
            int j0n = (t + 1) * TJ;
#pragma unroll
            for (int s = 0; s < VLD; ++s) {
                int idx = tid + s * 256;
                int j = idx / (F / 4), fq = idx % (F / 4);
                vreg[s] = reinterpret_cast<const float4*>(
                    V + ((size_t)b * N + j0n + j) * F)[fq];
            }
#pragma unroll
            for (int s = 0; s < 2; ++s) {
                int jj = s * 16 + wid * 2 + bjh;
                const float* cp = C + ((size_t)b * N + j0n + jj) * 3;
                cxa[s] = cp[0]; cya[s] = cp[1]; cza[s] = cp[2];
            }
        }
        // mma on tile t (AT layout: af from A[cur][jcol][m])
#pragma unroll
        for (int ks = 0; ks < 4; ++ks) {
            uint32_t af[TM][4];
#pragma unroll
            for (int tm = 0; tm < TM; ++tm) {
                int r = warp_m * WM + tm * 16;
                af[tm][0] = S.A[cur][ks * 8 + cc][r + g];
                af[tm][1] = S.A[cur][ks * 8 + cc][r + g + 8];
                af[tm][2] = S.A[cur][ks * 8 + cc + 4][r + g];
                af[tm][3] = S.A[cur][ks * 8 + cc + 4][r + g + 8];
            }
#pragma unroll
            for (int tn = 0; tn < TN; ++tn) {
                int nb = warp_n * WN + tn * 8;
                uint32_t b0 = S.Vt[cur][ks * 8 + cc][nb + g];
                uint32_t b1 = S.Vt[cur][ks * 8 + cc + 4][nb + g];
#pragma unroll
                for (int tm = 0; tm < TM; ++tm)
                    mma8(acc[tm][tn], af[tm][0], af[tm][1], af[tm][2], af[tm][3], b0, b1);
            }
        }
        // stage + build tile t+1
        if (more) {
#pragma unroll
            for (int s = 0; s < VLD; ++s) {
                int idx = tid + s * 256;
                int j = idx / (F / 4), fq = idx % (F / 4);
                S.Vt[nxt][j][fq * 4 + 0] = f2tf(vreg[s].x);
                S.Vt[nxt][j][fq * 4 + 1] = f2tf(vreg[s].y);
                S.Vt[nxt][j][fq * 4 + 2] = f2tf(vreg[s].z);
                S.Vt[nxt][j][fq * 4 + 3] = f2tf(vreg[s].w);
            }
            build(nxt, cxa, cya, cza);
        }
        __syncthreads();   // single barrier per tile
    }

    // write M section of X: GEMM row m = i*8+k
#pragma unroll
    for (int tm = 0; tm < TM; ++tm) {
#pragma unroll
        for (int half = 0; half < 2; ++half) {
            int m = warp_m * WM + tm * 16 + g + half * 8;
            int i = m >> 3, k = m & 7;
            float* xr = X + ((size_t)b * N + i0 + i) * XW + F + k * F + warp_n * WN;
#pragma unroll
            for (int tn = 0; tn < TN; ++tn) {
                float2 o;
                o.x = acc[tm][tn][half * 2 + 0];
                o.y = acc[tm][tn][half * 2 + 1];
                *reinterpret_cast<float2*>(xr + tn * 8 + 2 * cc) = o;
            }
        }
    }
}

// =================================================================
// tf32 GEMM + tanh + BN + fused 2:1 row pooling (R4 version)
// =================================================================
template <int NIN>
__global__ __launch_bounds__(256) void gemm_pool(
        const float* __restrict__ A, const float* __restrict__ Wt,
        const float* __restrict__ bias, const float* __restrict__ bng,
        const float* __restrict__ bnb, float* __restrict__ Out,
        int Kd, int Nc) {
    constexpr int BM = 128, BN = 64, BK = 32;
    constexpr int TM = 2, TN = 4;                // warps 4(M) x 2(N)
    __shared__ uint32_t As[BM][BK + 4];
    __shared__ uint32_t Bs[BK][BN + 8];
    const int bm = blockIdx.y * BM, bn = blockIdx.x * BN;
    const int tid = threadIdx.x, wid = tid >> 5, lane = tid & 31;
    const int g = lane >> 2, cc = lane & 3;
    const int warp_m = wid >> 1, warp_n = wid & 1;

    float acc[TM][TN][4];
#pragma unroll
    for (int tm = 0; tm < TM; ++tm)
#pragma unroll
        for (int tn = 0; tn < TN; ++tn)
#pragma unroll
            for (int q = 0; q < 4; ++q) acc[tm][tn][q] = 0.f;

    float4 ra[4], rb[2];
    const int nk = Kd / BK;

    {
#pragma unroll
        for (int s = 0; s < 4; ++s) {
            int idx = tid + s * 256, r = idx >> 3, cq = idx & 7;
            ra[s] = *reinterpret_cast<const float4*>(A + (size_t)(bm + r) * Kd + cq * 4);
        }
#pragma unroll
        for (int s = 0; s < 2; ++s) {
            int idx = tid + s * 256, kr = idx >> 4, cq = idx & 15;
            rb[s] = *reinterpret_cast<const float4*>(Wt + (size_t)kr * Nc + bn + cq * 4);
        }
    }

    for (int kt = 0; kt < nk; ++kt) {
#pragma unroll
        for (int s = 0; s < 4; ++s) {
            int idx = tid + s * 256, r = idx >> 3, cq = idx & 7;
            As[r][cq * 4 + 0] = f2tf(ra[s].x);
            As[r][cq * 4 + 1] = f2tf(ra[s].y);
            As[r][cq * 4 + 2] = f2tf(ra[s].z);
            As[r][cq * 4 + 3] = f2tf(ra[s].w);
        }
#pragma unroll
        for (int s = 0; s < 2; ++s) {
            int idx = tid + s * 256, kr = idx >> 4, cq = idx & 15;
            Bs[kr][cq * 4 + 0] = f2tf(rb[s].x);
            Bs[kr][cq * 4 + 1] = f2tf(rb[s].y);
            Bs[kr][cq * 4 + 2] = f2tf(rb[s].z);
            Bs[kr][cq * 4 + 3] = f2tf(rb[s].w);
        }
        __syncthreads();
        if (kt + 1 < nk) {
            int k0 = (kt + 1) * BK;
#pragma unroll
            for (int s = 0; s < 4; ++s) {
                int idx = tid + s * 256, r = idx >> 3, cq = idx & 7;
                ra[s] = *reinterpret_cast<const float4*>(
                    A + (size_t)(bm + r) * Kd + k0 + cq * 4);
            }
#pragma unroll
            for (int s = 0; s < 2; ++s) {
                int idx = tid + s * 256, kr = idx >> 4, cq = idx & 15;
                rb[s] = *reinterpret_cast<const float4*>(
                    Wt + (size_t)(k0 + kr) * Nc + bn + cq * 4);
            }
        }
#pragma unroll
        for (int ks = 0; ks < 4; ++ks) {
            uint32_t af[TM][4];
#pragma unroll
            for (int tm = 0; tm < TM; ++tm) {
                int r = warp_m * 32 + tm * 16;
                af[tm][0] = As[r + g][ks * 8 + cc];
                af[tm][1] = As[r + g + 8][ks * 8 + cc];
                af[tm][2] = As[r + g][ks * 8 + cc + 4];
                af[tm][3] = As[r + g + 8][ks * 8 + cc + 4];
            }
#pragma unroll
            for (int tn = 0; tn < TN; ++tn) {
                int nb = warp_n * 32 + tn * 8;
                uint32_t b0 = Bs[ks * 8 + cc][nb + g];
                uint32_t b1 = Bs[ks * 8 + cc + 4][nb + g];
#pragma unroll
                for (int tm = 0; tm < TM; ++tm)
                    mma8(acc[tm][tn], af[tm][0], af[tm][1], af[tm][2], af[tm][3], b0, b1);
            }
        }
        __syncthreads();
    }

    const bool wr = ((g & 1) == 0);
#pragma unroll
    for (int tm = 0; tm < TM; ++tm) {
#pragma unroll
        for (int half = 0; half < 2; ++half) {
            int r = bm + warp_m * 32 + tm * 16 + g + half * 8;
#pragma unroll
            for (int tn = 0; tn < TN; ++tn) {
                int col = bn + warp_n * 32 + tn * 8 + 2 * cc;
                float h0 = bng[col] * tanhf(acc[tm][tn][half * 2 + 0] + bias[col]) + bnb[col];
                float h1 = bng[col + 1] * tanhf(acc[tm][tn][half * 2 + 1] + bias[col + 1]) + bnb[col + 1];
                float p0 = 0.5f * (h0 + __shfl_down_sync(0xffffffffu, h0, 4));
                float p1 = 0.5f * (h1 + __shfl_down_sync(0xffffffffu, h1, 4));
                if (wr) {
                    int pr = (r / NIN) * (NIN / 2) + (r % NIN) / 2;
                    *reinterpret_cast<float2*>(Out + (size_t)pr * Nc + col) =
                        make_float2(p0, p1);
                }
            }
        }
    }
}

// ---------------- coord pooling (tiny) ----------------
__global__ void poolC_kernel(const float* __restrict__ C, float* __restrict__ C1) {
    int idx = blockIdx.x * blockDim.x + threadIdx.x;
    if (idx >= BB * N1 * 3) return;
    int c = idx % 3;
    int i = (idx / 3) % N1;
    int b = idx / (3 * N1);
    size_t base = ((size_t)b * N0 + 2 * i) * 3 + c;
    C1[idx] = 0.5f * (C[base] + C[base + 3]);
}

// ---------------- FC: split-K partials (fp32, deterministic) ----------------
__global__ __launch_bounds__(128) void fc_partial(const float* __restrict__ Flat,
                                                  const float* __restrict__ W) {
    constexpr int KCH = FLATD / 128;   // 256
    const int kb = blockIdx.x * KCH;
    const int tid = threadIdx.x;
    __shared__ float sF[BB][KCH];
    for (int t = tid; t < BB * KCH / 4; t += 128) {
        int b = t / (KCH / 4), kq = t % (KCH / 4);
        *reinterpret_cast<float4*>(&sF[b][kq * 4]) =
            *reinterpret_cast<const float4*>(Flat + (size_t)b * FLATD + kb + kq * 4);
    }
    __syncthreads();

    float4 acc[BB];
#pragma unroll
    for (int b = 0; b < BB; ++b) acc[b] = make_float4(0.f, 0.f, 0.f, 0.f);

    const float* wp = W + (size_t)kb * FC_OUT + tid * 4;
    for (int k = 0; k < KCH; k += 4) {
        float4 w0 = *reinterpret_cast<const float4*>(wp + (size_t)(k + 0) * FC_OUT);
        float4 w1 = *reinterpret_cast<const float4*>(wp + (size_t)(k + 1) * FC_OUT);
        float4 w2 = *reinterpret_cast<const float4*>(wp + (size_t)(k + 2) * FC_OUT);
        float4 w3 = *reinterpret_cast<const float4*>(wp + (size_t)(k + 3) * FC_OUT);
#pragma unroll
        for (int b = 0; b < BB; ++b) {
            float4 f = *reinterpret_cast<float4*>(&sF[b][k]);
            acc[b].x += f.x * w0.x + f.y * w1.x + f.z * w2.x + f.w * w3.x;
            acc[b].y += f.x * w0.y + f.y * w1.y + f.z * w2.y + f.w * w3.y;
            acc[b].z += f.x * w0.z + f.y * w1.z + f.z * w2.z + f.w * w3.z;
            acc[b].w += f.x * w0.w + f.y * w1.w + f.z * w2.w + f.w * w3.w;
        }
    }
#pragma unroll
    for (int b = 0; b < BB; ++b)
        *reinterpret_cast<float4*>(&g_part[blockIdx.x][b * FC_OUT + tid * 4]) = acc[b];
}

__global__ void fc_finalize(const float* __restrict__ fcb, float* __restrict__ out) {
    int idx = blockIdx.x * blockDim.x + threadIdx.x;
    if (idx >= BB * FC_OUT) return;
    int col = idx & (FC_OUT - 1);
    float s = fcb[col];
#pragma unroll
    for (int t = 0; t < 128; ++t) s += g_part[t][idx];
    out[idx] = 1.f / (1.f + __expf(-s));
}

// ---------------- launch ----------------
extern "C" void kernel_launch(void* const* d_in, const int* in_sizes, int n_in,
                              void* d_out, int out_size) {
    const float* V    = (const float*)d_in[0];
    const float* C    = (const float*)d_in[1];
    const float* gkw0 = (const float*)d_in[2];
    const float* gkb0 = (const float*)d_in[3];
    const float* acw0 = (const float*)d_in[4];
    const float* acb0 = (const float*)d_in[5];
    const float* gcw0 = (const float*)d_in[6];
    const float* gcb0 = (const float*)d_in[7];
    const float* bng0 = (const float*)d_in[8];
    const float* bnb0 = (const float*)d_in[9];
    const float* gkw1 = (const float*)d_in[10];
    const float* gkb1 = (const float*)d_in[11];
    const float* acw1 = (const float*)d_in[12];
    const float* acb1 = (const float*)d_in[13];
    const float* gcw1 = (const float*)d_in[14];
    const float* gcb1 = (const float*)d_in[15];
    const float* bng1 = (const float*)d_in[16];
    const float* bnb1 = (const float*)d_in[17];
    const float* fcw  = (const float*)d_in[18];
    const float* fcb  = (const float*)d_in[19];
    float* out = (float*)d_out;

    float *X0, *H0p, *C1, *X1, *Flat;
    cudaGetSymbolAddress((void**)&X0, g_X0);
    cudaGetSymbolAddress((void**)&H0p, g_H0p);
    cudaGetSymbolAddress((void**)&C1, g_C1);
    cudaGetSymbolAddress((void**)&X1, g_X1);
    cudaGetSymbolAddress((void**)&Flat, g_Flat);

    const int smsg0 = (int)sizeof(MsgSmem<F0c>);
    const int smsg1 = (int)sizeof(MsgSmem<F1c>);
    cudaFuncSetAttribute(msg_kernel<F0c, N0>,
                         cudaFuncAttributeMaxDynamicSharedMemorySize, smsg0);
    cudaFuncSetAttribute(msg_kernel<F1c, N1>,
                         cudaFuncAttributeMaxDynamicSharedMemorySize, smsg1);

    // layer 0
    msg_kernel<F0c, N0><<<dim3(N0 / 16, BB), 256, smsg0>>>(
        V, C, gkw0, gkb0, acw0, acb0, X0);
    gemm_pool<N0><<<dim3(F1c / 64, BB * N0 / 128), 256>>>(
        X0, gcw0, gcb0, bng0, bnb0, H0p, (KK + 1) * F0c, F1c);
    poolC_kernel<<<(BB * N1 * 3 + 255) / 256, 256>>>(C, C1);

    // layer 1
    msg_kernel<F1c, N1><<<dim3(N1 / 16, BB), 256, smsg1>>>(
        H0p, C1, gkw1, gkb1, acw1, acb1, X1);
    gemm_pool<N1><<<dim3(F2c / 64, BB * N1 / 128), 256>>>(
        X1, gcw1, gcb1, bng1, bnb1, Flat, (KK + 1) * F1c, F2c);

    // FC head (fp32)
    fc_partial<<<128, 128>>>(Flat, fcw);
    fc_finalize<<<(BB * FC_OUT + 255) / 256, 256>>>(fcb, out);
}